// round 14
// baseline (speedup 1.0000x reference)
#include <cuda_runtime.h>
#include <cuda_fp16.h>
#include <math.h>

#define NN  100000      // nodes  (< 2^17)
#define NE  3200000     // edges (divisible by 4)
#define DH  64
#define DTXF 16
#define DTX  32
#define BB  16384
#define BN_EPS 1e-5f

#define SCAN_BLK 1024
#define NSCAN ((NN + SCAN_BLK - 1) / SCAN_BLK)   // 98

#define GEMMB   ((NN + 63) / 64)                 // 1563 gemm tiles (64 rows, 256 thr)
#define E4      (NE / 4)                         // 800000 4-edge groups
#define CNT4B   (E4 / 256)                       // 3125 count blocks (exact)
#define FILL4B  (E4 / 256)                       // 3125 fill blocks (exact)
#define FLAGB   (BB / 256)                       // 64 flag blocks

#define W_FIX   1048576.0f                       // 2^20 degree fixed-point
#define MASK44  ((1ULL << 44) - 1)
#define WQ_SCALE 32767.0f                        // 15-bit weight quant

// ---------------- scratch (device globals; self-resetting or overwritten) -------
__device__ float              g_h   [NN * DH];   // ONLY flagged rows (agg1 -> mlp)
__device__ __half2            g_xh0 [NN * 32];   // fp16 rows of layer-0 h@W0
__device__ __half2            g_xh1 [NN * 32];   // fp16 rows of layer-1 h@W1
__device__ unsigned long long g_pack[NN];        // count<<44 | degw_fix ; reset in scan23
__device__ float              g_dinv[NN];
__device__ int                g_rs  [NN + 1];    // CSR row starts (by dst)
__device__ int                g_bsum[NSCAN];
__device__ int                g_need[NN];        // reset in sparse k_agg1
__device__ unsigned           g_rank[NE];        // wq15<<17 | rank-within-dst-row
__device__ unsigned           g_cedge[NE];       // CSR: src<<15 | quant(w*dinv[src])

// ---------------- 1. count (4 edges/thread) + MLP need-flags ---------------------
__global__ void k_cnt(const int* __restrict__ dst, const float* __restrict__ ew,
                      const int* __restrict__ tsl, const int* __restrict__ trl,
                      const int* __restrict__ ptr)
{
    int tid = threadIdx.x;
    if (blockIdx.x < CNT4B) {
        int e4 = blockIdx.x * 256 + tid;
        int4   d4 = ((const int4*)dst)[e4];
        float4 w4 = ((const float4*)ew)[e4];
        int   dd[4] = {d4.x, d4.y, d4.z, d4.w};
        float ww[4] = {w4.x, w4.y, w4.z, w4.w};
        unsigned rr[4];
        #pragma unroll
        for (int k = 0; k < 4; k++) {
            unsigned long long v = (1ULL << 44)
                | (unsigned long long)__float2uint_rn(ww[k] * W_FIX);
            unsigned long long old = atomicAdd(&g_pack[dd[k]], v);
            rr[k] = (unsigned)(old >> 44)
                  | (__float2uint_rn(ww[k] * WQ_SCALE) << 17);
        }
        ((uint4*)g_rank)[e4] = make_uint4(rr[0], rr[1], rr[2], rr[3]);
    } else {
        int row = (blockIdx.x - CNT4B) * 256 + tid;
        if (row < BB) {
            int off = ptr[row];
            g_need[tsl[row] + off] = 1;
            g_need[trl[row] + off] = 1;
        }
    }
}

// ---------------- 2. scan within 1024-blocks ------------------------------------
__global__ void k_scan1()
{
    __shared__ int s[SCAN_BLK];
    int tid = threadIdx.x;
    int i = blockIdx.x * SCAN_BLK + tid;
    int v = (i < NN) ? (int)(g_pack[i] >> 44) : 0;
    s[tid] = v;
    __syncthreads();
    #pragma unroll
    for (int off = 1; off < SCAN_BLK; off <<= 1) {
        int t = (tid >= off) ? s[tid - off] : 0;
        __syncthreads();
        s[tid] += t;
        __syncthreads();
    }
    if (i < NN) g_rs[i] = s[tid] - v;            // exclusive within block
    if (tid == SCAN_BLK - 1) g_bsum[blockIdx.x] = s[tid];
}

// ---------------- 3. block-offset scan + finalize + dinv (+ reset pack) ---------
__global__ void k_scan23()
{
    __shared__ int bs[NSCAN];
    __shared__ int total_s;
    int tid = threadIdx.x;
    if (tid < NSCAN) bs[tid] = g_bsum[tid];
    __syncthreads();
    if (tid == 0) {
        int run = 0;
        for (int k = 0; k < NSCAN; k++) { int v = bs[k]; bs[k] = run; run += v; }
        total_s = run;
    }
    __syncthreads();
    int i = blockIdx.x * blockDim.x + tid;
    if (i == 0) g_rs[NN] = total_s;              // = NE
    if (i >= NN) return;
    int r = g_rs[i] + bs[i / SCAN_BLK];
    g_rs[i] = r;
    unsigned long long p = g_pack[i];
    g_pack[i] = 0ULL;                            // self-reset for next call
    float d = (float)(p & MASK44) * (1.0f / W_FIX) + 1.0f;  // + self-loop
    g_dinv[i] = rsqrtf(d);                        // d >= 1
}

// ---------------- 4. CSR fill ∥ gemm-L0 (emb gather) -> g_xh0 --------------------
__global__ void __launch_bounds__(256)
k_fillgemm0(const float* __restrict__ W,
            const int* __restrict__ ids, const float* __restrict__ emb,
            const int* __restrict__ src, const int* __restrict__ dst)
{
    __shared__ float4 hs4[64][17];
    __shared__ float4 ws4[64][17];
    int tid = threadIdx.x;
    int bx  = blockIdx.x;

    if (bx < FILL4B) {
        // ---- fill: 4 edges/thread, atomic-free ----
        int e4 = bx * 256 + tid;
        int4  d4 = ((const int4*)dst)[e4];
        int4  s4 = ((const int4*)src)[e4];
        uint4 r4 = ((const uint4*)g_rank)[e4];
        int      dd[4] = {d4.x, d4.y, d4.z, d4.w};
        int      ss[4] = {s4.x, s4.y, s4.z, s4.w};
        unsigned rw[4] = {r4.x, r4.y, r4.z, r4.w};
        float    dv[4];
        #pragma unroll
        for (int k = 0; k < 4; k++) dv[k] = g_dinv[ss[k]];
        #pragma unroll
        for (int k = 0; k < 4; k++) {
            float wq = (float)(rw[k] >> 17) * (1.0f / WQ_SCALE) * dv[k];
            int pos  = g_rs[dd[k]] + (int)(rw[k] & 0x1FFFFu);
            g_cedge[pos] = ((unsigned)ss[k] << 15)
                         | __float2uint_rn(wq * WQ_SCALE);
        }
        return;
    }

    // ---- gemm-L0: 64 rows gathered from emb[ids[row]] ----
    int r0 = (bx - FILL4B) * 64;
    #pragma unroll
    for (int ii = 0; ii < 4; ii++) {
        int i = ii * 256 + tid;
        int r = i >> 4, c = i & 15;
        int row = r0 + r;
        float4 v = make_float4(0.f, 0.f, 0.f, 0.f);
        if (row < NN) v = ((const float4*)(emb + (long)ids[row] * DH))[c];
        hs4[r][c] = v;
        ws4[r][c] = ((const float4*)W)[i];
    }
    __syncthreads();

    int tx = tid & 15, ty = tid >> 4;
    float4 acc[4];
    #pragma unroll
    for (int r = 0; r < 4; r++) acc[r] = make_float4(0.f, 0.f, 0.f, 0.f);
    #pragma unroll
    for (int kg = 0; kg < 16; kg++) {
        float4 w0 = ws4[kg * 4 + 0][tx];
        float4 w1 = ws4[kg * 4 + 1][tx];
        float4 w2 = ws4[kg * 4 + 2][tx];
        float4 w3 = ws4[kg * 4 + 3][tx];
        #pragma unroll
        for (int r = 0; r < 4; r++) {
            float4 a = hs4[ty * 4 + r][kg];
            acc[r].x += a.x * w0.x + a.y * w1.x + a.z * w2.x + a.w * w3.x;
            acc[r].y += a.x * w0.y + a.y * w1.y + a.z * w2.y + a.w * w3.y;
            acc[r].z += a.x * w0.z + a.y * w1.z + a.z * w2.z + a.w * w3.z;
            acc[r].w += a.x * w0.w + a.y * w1.w + a.z * w2.w + a.w * w3.w;
        }
    }
    #pragma unroll
    for (int r = 0; r < 4; r++) {
        int row = r0 + ty * 4 + r;
        if (row < NN) {
            g_xh0[row * 32 + tx * 2]     = __floats2half2_rn(acc[r].x, acc[r].y);
            g_xh0[row * 32 + tx * 2 + 1] = __floats2half2_rn(acc[r].z, acc[r].w);
        }
    }
}

// ---------------- 5. FUSED agg0 (into smem) + gemm-L1 -> g_xh1 -------------------
// block = 64 nodes; 8 warps aggregate 8 nodes each; h0 never hits global memory.
__global__ void __launch_bounds__(256)
k_agggemm1(const float* __restrict__ W, const float* __restrict__ b)
{
    __shared__ float4 hs4[64][17];
    __shared__ float4 ws4[64][17];
    int tid  = threadIdx.x;
    int lane = tid & 31;
    int wid  = tid >> 5;                         // 0..7
    int r0   = blockIdx.x * 64;

    // load W1 (independent of agg)
    #pragma unroll
    for (int ii = 0; ii < 4; ii++) {
        int i = ii * 256 + tid;
        ws4[i >> 4][i & 15] = ((const float4*)W)[i];
    }

    const float  wdq = 1.0f / WQ_SCALE;
    const float2 bb  = ((const float2*)b)[lane];

    // aggregate 8 nodes per warp; result rows -> smem
    #pragma unroll
    for (int n = 0; n < 8; n++) {
        int node = r0 + wid * 8 + n;
        if (node >= NN) break;

        int start = g_rs[node];
        int end   = g_rs[node + 1];
        float di  = g_dinv[node];

        float2 xs  = __half22float2(__ldg(&g_xh0[node * 32 + lane]));
        float2 acc = make_float2(xs.x * di, xs.y * di);

        int cnt = end - start;
        int n8  = start + (cnt & ~7);
        int j = start;
        for (; j < n8; j += 8) {
            unsigned e[8];
            #pragma unroll
            for (int k = 0; k < 8; k++) e[k] = __ldg(&g_cedge[j + k]);
            float2 v[8];
            #pragma unroll
            for (int k = 0; k < 8; k++)
                v[k] = __half22float2(__ldg(&g_xh0[(e[k] >> 15) * 32 + lane]));
            #pragma unroll
            for (int k = 0; k < 8; k++) {
                float nn = (float)(e[k] & 0x7FFFu) * wdq;
                acc.x += nn * v[k].x;
                acc.y += nn * v[k].y;
            }
        }
        for (; j < end; j++) {
            unsigned e0 = __ldg(&g_cedge[j]);
            float2 v0 = __half22float2(__ldg(&g_xh0[(e0 >> 15) * 32 + lane]));
            float nn = (float)(e0 & 0x7FFFu) * wdq;
            acc.x += nn * v0.x;
            acc.y += nn * v0.y;
        }

        float2 o = make_float2(fmaxf(acc.x * di + bb.x, 0.0f),
                               fmaxf(acc.y * di + bb.y, 0.0f));
        ((float2*)&hs4[wid * 8 + n][0])[lane] = o;   // row-local smem store
    }
    __syncthreads();

    // gemm-L1 from smem tile
    int tx = tid & 15, ty = tid >> 4;
    float4 acc[4];
    #pragma unroll
    for (int r = 0; r < 4; r++) acc[r] = make_float4(0.f, 0.f, 0.f, 0.f);
    #pragma unroll
    for (int kg = 0; kg < 16; kg++) {
        float4 w0 = ws4[kg * 4 + 0][tx];
        float4 w1 = ws4[kg * 4 + 1][tx];
        float4 w2 = ws4[kg * 4 + 2][tx];
        float4 w3 = ws4[kg * 4 + 3][tx];
        #pragma unroll
        for (int r = 0; r < 4; r++) {
            float4 a = hs4[ty * 4 + r][kg];
            acc[r].x += a.x * w0.x + a.y * w1.x + a.z * w2.x + a.w * w3.x;
            acc[r].y += a.x * w0.y + a.y * w1.y + a.z * w2.y + a.w * w3.y;
            acc[r].z += a.x * w0.z + a.y * w1.z + a.z * w2.z + a.w * w3.z;
            acc[r].w += a.x * w0.w + a.y * w1.w + a.z * w2.w + a.w * w3.w;
        }
    }
    #pragma unroll
    for (int r = 0; r < 4; r++) {
        int row = r0 + ty * 4 + r;
        if (row < NN) {
            g_xh1[row * 32 + tx * 2]     = __floats2half2_rn(acc[r].x, acc[r].y);
            g_xh1[row * 32 + tx * 2 + 1] = __floats2half2_rn(acc[r].z, acc[r].w);
        }
    }
}

// ---------------- 6. sparse agg1 (flagged nodes) -> g_h --------------------------
__global__ void k_agg1(const float* __restrict__ b)
{
    int warp = blockIdx.x * (blockDim.x >> 5) + (threadIdx.x >> 5);
    if (warp >= NN) return;
    int lane = threadIdx.x & 31;

    int need = g_need[warp];                     // all lanes read (broadcast)
    __syncwarp();
    if (!need) return;
    if (lane == 0) g_need[warp] = 0;             // self-reset for next call

    int start = g_rs[warp];
    int end   = g_rs[warp + 1];
    float di  = g_dinv[warp];

    float2 xs  = __half22float2(__ldg(&g_xh1[warp * 32 + lane]));
    float2 acc = make_float2(xs.x * di, xs.y * di);

    const float wdq = 1.0f / WQ_SCALE;
    int cnt = end - start;
    int n8  = start + (cnt & ~7);
    int j = start;
    for (; j < n8; j += 8) {
        unsigned e[8];
        #pragma unroll
        for (int k = 0; k < 8; k++) e[k] = __ldg(&g_cedge[j + k]);
        float2 v[8];
        #pragma unroll
        for (int k = 0; k < 8; k++)
            v[k] = __half22float2(__ldg(&g_xh1[(e[k] >> 15) * 32 + lane]));
        #pragma unroll
        for (int k = 0; k < 8; k++) {
            float n = (float)(e[k] & 0x7FFFu) * wdq;
            acc.x += n * v[k].x;
            acc.y += n * v[k].y;
        }
    }
    for (; j < end; j++) {
        unsigned e0 = __ldg(&g_cedge[j]);
        float2 v0 = __half22float2(__ldg(&g_xh1[(e0 >> 15) * 32 + lane]));
        float n = (float)(e0 & 0x7FFFu) * wdq;
        acc.x += n * v0.x;
        acc.y += n * v0.y;
    }

    float2 bb = ((const float2*)b)[lane];
    float2 o  = make_float2(fmaxf(acc.x * di + bb.x, 0.0f),
                            fmaxf(acc.y * di + bb.y, 0.0f));
    ((float2*)g_h)[warp * 32 + lane] = o;
}

// ---------------- 7. fused MLP head (one warp per row) ---------------------------
__global__ void k_mlp(const int* __restrict__ tsl, const int* __restrict__ trl,
                      const int* __restrict__ ptr, const float* __restrict__ txf,
                      const float* __restrict__ Wtx, const float* __restrict__ btx,
                      const float* __restrict__ Wc1, const float* __restrict__ bc1,
                      const float* __restrict__ g1,  const float* __restrict__ beta1,
                      const float* __restrict__ Wc2, const float* __restrict__ bc2,
                      const float* __restrict__ g2,  const float* __restrict__ beta2,
                      const float* __restrict__ Wc3, const float* __restrict__ bc3,
                      float* __restrict__ out)
{
    __shared__ float Wc1s[160 * 64];
    for (int i = threadIdx.x; i < 160 * 64; i += blockDim.x) Wc1s[i] = Wc1[i];
    __syncthreads();

    const int lane = threadIdx.x & 31;
    const int row  = blockIdx.x * (blockDim.x >> 5) + (threadIdx.x >> 5);
    if (row >= BB) return;

    const float invs = rsqrtf(1.0f + BN_EPS);
    const unsigned FULL = 0xffffffffu;

    int off  = ptr[row];
    int sidx = tsl[row] + off;
    int ridx = trl[row] + off;

    float f = (lane < DTXF) ? txf[row * DTXF + lane] : 0.0f;
    float acct = __ldg(&btx[lane]);
    #pragma unroll
    for (int k = 0; k < DTXF; k++) {
        float tk = __shfl_sync(FULL, f, k);
        acct += tk * __ldg(&Wtx[k * DTX + lane]);
    }
    float txv = fmaxf(acct, 0.0f);

    float zr[5];
    zr[0] = g_h[sidx * DH + lane];
    zr[1] = g_h[sidx * DH + 32 + lane];
    zr[2] = g_h[ridx * DH + lane];
    zr[3] = g_h[ridx * DH + 32 + lane];
    zr[4] = txv;

    float2 a = make_float2(0.f, 0.f);
    #pragma unroll
    for (int k = 0; k < 160; k++) {
        float zk = __shfl_sync(FULL, zr[k >> 5], k & 31);
        float2 w = *(const float2*)&Wc1s[k * 64 + 2 * lane];
        a.x += zk * w.x;
        a.y += zk * w.y;
    }
    int c0 = 2 * lane, c1 = 2 * lane + 1;
    float z1x = fmaxf((a.x + __ldg(&bc1[c0])) * (__ldg(&g1[c0]) * invs) + __ldg(&beta1[c0]), 0.0f);
    float z1y = fmaxf((a.y + __ldg(&bc1[c1])) * (__ldg(&g1[c1]) * invs) + __ldg(&beta1[c1]), 0.0f);

    float acc2 = 0.0f;
    #pragma unroll
    for (int k = 0; k < DH; k++) {
        float zk = __shfl_sync(FULL, (k & 1) ? z1y : z1x, k >> 1);
        acc2 += zk * __ldg(&Wc2[k * 32 + lane]);
    }
    float z2v = fmaxf((acc2 + __ldg(&bc2[lane])) * (__ldg(&g2[lane]) * invs) + __ldg(&beta2[lane]), 0.0f);

    float p = z2v * __ldg(&Wc3[lane]);
    #pragma unroll
    for (int o = 16; o > 0; o >>= 1) p += __shfl_xor_sync(FULL, p, o);
    if (lane == 0) out[row] = p + __ldg(&bc3[0]);
}

// =============================== launch ========================================
extern "C" void kernel_launch(void* const* d_in, const int* in_sizes, int n_in,
                              void* d_out, int out_size)
{
    const int*   ids  = (const int*)  d_in[0];
    const int*   ei   = (const int*)  d_in[1];
    const float* ew   = (const float*)d_in[2];
    const int*   tsl  = (const int*)  d_in[3];
    const int*   trl  = (const int*)  d_in[4];
    const int*   ptr  = (const int*)  d_in[5];
    const float* txf  = (const float*)d_in[6];
    const float* emb  = (const float*)d_in[7];
    const float* W0   = (const float*)d_in[8];
    const float* b0   = (const float*)d_in[9];
    const float* W1   = (const float*)d_in[10];
    const float* b1   = (const float*)d_in[11];
    const float* Wtx  = (const float*)d_in[12];
    const float* btx  = (const float*)d_in[13];
    const float* Wc1  = (const float*)d_in[14];
    const float* bc1  = (const float*)d_in[15];
    const float* g1   = (const float*)d_in[16];
    const float* beta1= (const float*)d_in[17];
    const float* Wc2  = (const float*)d_in[18];
    const float* bc2  = (const float*)d_in[19];
    const float* g2   = (const float*)d_in[20];
    const float* beta2= (const float*)d_in[21];
    const float* Wc3  = (const float*)d_in[22];
    const float* bc3  = (const float*)d_in[23];
    float* out = (float*)d_out;

    const int* src = ei;
    const int* dst = ei + NE;

    // 1 count (rank+wq packed) + need-flags
    k_cnt<<<CNT4B + FLAGB, 256>>>(dst, ew, tsl, trl, ptr);
    // 2-3 scan + dinv
    k_scan1 <<<NSCAN, SCAN_BLK>>>();
    k_scan23<<<(NN + 255) / 256, 256>>>();
    // 4 CSR fill ∥ gemm-L0 -> g_xh0
    k_fillgemm0<<<FILL4B + GEMMB, 256>>>(W0, ids, emb, src, dst);
    // 5 FUSED agg0 (smem) + gemm-L1 -> g_xh1   (h0 never hits DRAM/L2 arrays)
    k_agggemm1<<<GEMMB, 256>>>(W1, b0);
    // 6 sparse agg1 (flagged nodes) -> g_h
    k_agg1<<<(NN + 7) / 8, 256>>>(b1);
    // 7 fused MLP head
    k_mlp<<<BB / 8, 256>>>(tsl, trl, ptr, txf,
                           Wtx, btx, Wc1, bc1, g1, beta1,
                           Wc2, bc2, g2, beta2, Wc3, bc3, out);
}

// round 15
// speedup vs baseline: 1.0636x; 1.0636x over previous
#include <cuda_runtime.h>
#include <cuda_fp16.h>
#include <math.h>

#define NN  100000      // nodes  (< 2^17)
#define NE  3200000     // edges (divisible by 4)
#define DH  64
#define DTXF 16
#define DTX  32
#define BB  16384
#define BN_EPS 1e-5f

#define SCAN_BLK 1024
#define NSCAN ((NN + SCAN_BLK - 1) / SCAN_BLK)   // 98

#define GEMMB   ((NN + 63) / 64)                 // 1563 gemm tiles (64 rows, 256 thr)
#define E4      (NE / 4)                         // 800000 4-edge groups
#define CNT4B   (E4 / 256)                       // 3125 count blocks (exact)
#define FILL4B  (E4 / 256)                       // 3125 fill blocks (exact)

#define W_FIX   1048576.0f                       // 2^20 degree fixed-point
#define MASK44  ((1ULL << 44) - 1)
#define WQ_SCALE 32767.0f                        // 15-bit weight quant

// ---------------- scratch (device globals; self-resetting or overwritten) -------
__device__ __half2            g_xh0 [NN * 32];   // fp16 rows of h0@... = emb@W0
__device__ __half2            g_hh  [NN * 32];   // fp16 rows of h0 (agg0 output)
__device__ __half2            g_xh1 [NN * 32];   // fp16 rows of h0@W1
__device__ unsigned long long g_pack[NN];        // count<<44 | degw_fix ; reset in scan23
__device__ float              g_dinv[NN];
__device__ int                g_rs  [NN + 1];    // CSR row starts (by dst)
__device__ int                g_bsum[NSCAN];
__device__ unsigned           g_rank[NE];        // wq15<<17 | rank-within-dst-row
__device__ unsigned           g_cedge[NE];       // CSR: src<<15 | quant(w*dinv[src])

// ---------------- 1. count: 4 edges/thread, packed 64-bit atomic ----------------
__global__ void k_cnt(const int* __restrict__ dst, const float* __restrict__ ew)
{
    int e4 = blockIdx.x * 256 + threadIdx.x;
    int4   d4 = ((const int4*)dst)[e4];
    float4 w4 = ((const float4*)ew)[e4];
    int   dd[4] = {d4.x, d4.y, d4.z, d4.w};
    float ww[4] = {w4.x, w4.y, w4.z, w4.w};
    unsigned rr[4];
    #pragma unroll
    for (int k = 0; k < 4; k++) {
        unsigned long long v = (1ULL << 44)
            | (unsigned long long)__float2uint_rn(ww[k] * W_FIX);
        unsigned long long old = atomicAdd(&g_pack[dd[k]], v);
        rr[k] = (unsigned)(old >> 44)
              | (__float2uint_rn(ww[k] * WQ_SCALE) << 17);
    }
    ((uint4*)g_rank)[e4] = make_uint4(rr[0], rr[1], rr[2], rr[3]);
}

// ---------------- 2. scan within 1024-blocks ------------------------------------
__global__ void k_scan1()
{
    __shared__ int s[SCAN_BLK];
    int tid = threadIdx.x;
    int i = blockIdx.x * SCAN_BLK + tid;
    int v = (i < NN) ? (int)(g_pack[i] >> 44) : 0;
    s[tid] = v;
    __syncthreads();
    #pragma unroll
    for (int off = 1; off < SCAN_BLK; off <<= 1) {
        int t = (tid >= off) ? s[tid - off] : 0;
        __syncthreads();
        s[tid] += t;
        __syncthreads();
    }
    if (i < NN) g_rs[i] = s[tid] - v;            // exclusive within block
    if (tid == SCAN_BLK - 1) g_bsum[blockIdx.x] = s[tid];
}

// ---------------- 3. block-offset scan + finalize + dinv (+ reset pack) ---------
__global__ void k_scan23()
{
    __shared__ int bs[NSCAN];
    __shared__ int total_s;
    int tid = threadIdx.x;
    if (tid < NSCAN) bs[tid] = g_bsum[tid];
    __syncthreads();
    if (tid == 0) {
        int run = 0;
        for (int k = 0; k < NSCAN; k++) { int v = bs[k]; bs[k] = run; run += v; }
        total_s = run;
    }
    __syncthreads();
    int i = blockIdx.x * blockDim.x + tid;
    if (i == 0) g_rs[NN] = total_s;              // = NE
    if (i >= NN) return;
    int r = g_rs[i] + bs[i / SCAN_BLK];
    g_rs[i] = r;
    unsigned long long p = g_pack[i];
    g_pack[i] = 0ULL;                            // self-reset for next call
    float d = (float)(p & MASK44) * (1.0f / W_FIX) + 1.0f;  // + self-loop
    g_dinv[i] = rsqrtf(d);                        // d >= 1
}

// ---------------- 4. CSR fill ∥ gemm-L0 (emb gather) -> g_xh0 --------------------
__global__ void __launch_bounds__(256)
k_fillgemm0(const float* __restrict__ W,
            const int* __restrict__ ids, const float* __restrict__ emb,
            const int* __restrict__ src, const int* __restrict__ dst)
{
    __shared__ float4 hs4[64][17];
    __shared__ float4 ws4[64][17];
    int tid = threadIdx.x;
    int bx  = blockIdx.x;

    if (bx < FILL4B) {
        // ---- fill: 4 edges/thread, atomic-free ----
        int e4 = bx * 256 + tid;
        int4  d4 = ((const int4*)dst)[e4];
        int4  s4 = ((const int4*)src)[e4];
        uint4 r4 = ((const uint4*)g_rank)[e4];
        int      dd[4] = {d4.x, d4.y, d4.z, d4.w};
        int      ss[4] = {s4.x, s4.y, s4.z, s4.w};
        unsigned rw[4] = {r4.x, r4.y, r4.z, r4.w};
        float    dv[4];
        #pragma unroll
        for (int k = 0; k < 4; k++) dv[k] = g_dinv[ss[k]];
        #pragma unroll
        for (int k = 0; k < 4; k++) {
            float wq = (float)(rw[k] >> 17) * (1.0f / WQ_SCALE) * dv[k];
            int pos  = g_rs[dd[k]] + (int)(rw[k] & 0x1FFFFu);
            g_cedge[pos] = ((unsigned)ss[k] << 15)
                         | __float2uint_rn(wq * WQ_SCALE);
        }
        return;
    }

    // ---- gemm-L0: 64 rows gathered from emb[ids[row]] ----
    int r0 = (bx - FILL4B) * 64;
    #pragma unroll
    for (int ii = 0; ii < 4; ii++) {
        int i = ii * 256 + tid;
        int r = i >> 4, c = i & 15;
        int row = r0 + r;
        float4 v = make_float4(0.f, 0.f, 0.f, 0.f);
        if (row < NN) v = ((const float4*)(emb + (long)ids[row] * DH))[c];
        hs4[r][c] = v;
        ws4[r][c] = ((const float4*)W)[i];
    }
    __syncthreads();

    int tx = tid & 15, ty = tid >> 4;
    float4 acc[4];
    #pragma unroll
    for (int r = 0; r < 4; r++) acc[r] = make_float4(0.f, 0.f, 0.f, 0.f);
    #pragma unroll
    for (int kg = 0; kg < 16; kg++) {
        float4 w0 = ws4[kg * 4 + 0][tx];
        float4 w1 = ws4[kg * 4 + 1][tx];
        float4 w2 = ws4[kg * 4 + 2][tx];
        float4 w3 = ws4[kg * 4 + 3][tx];
        #pragma unroll
        for (int r = 0; r < 4; r++) {
            float4 a = hs4[ty * 4 + r][kg];
            acc[r].x += a.x * w0.x + a.y * w1.x + a.z * w2.x + a.w * w3.x;
            acc[r].y += a.x * w0.y + a.y * w1.y + a.z * w2.y + a.w * w3.y;
            acc[r].z += a.x * w0.z + a.y * w1.z + a.z * w2.z + a.w * w3.z;
            acc[r].w += a.x * w0.w + a.y * w1.w + a.z * w2.w + a.w * w3.w;
        }
    }
    #pragma unroll
    for (int r = 0; r < 4; r++) {
        int row = r0 + ty * 4 + r;
        if (row < NN) {
            g_xh0[row * 32 + tx * 2]     = __floats2half2_rn(acc[r].x, acc[r].y);
            g_xh0[row * 32 + tx * 2 + 1] = __floats2half2_rn(acc[r].z, acc[r].w);
        }
    }
}

// ---------------- 5. dense agg0 -> g_hh (fp16, bias+relu) ------------------------
__global__ void k_agg0(const float* __restrict__ b)
{
    int warp = blockIdx.x * (blockDim.x >> 5) + (threadIdx.x >> 5);
    if (warp >= NN) return;
    int lane = threadIdx.x & 31;

    int start = g_rs[warp];
    int end   = g_rs[warp + 1];
    float di  = g_dinv[warp];

    float2 xs  = __half22float2(__ldg(&g_xh0[warp * 32 + lane]));
    float2 acc = make_float2(xs.x * di, xs.y * di);

    const float wdq = 1.0f / WQ_SCALE;
    int cnt = end - start;
    int n8  = start + (cnt & ~7);
    int j = start;
    for (; j < n8; j += 8) {
        unsigned e[8];
        #pragma unroll
        for (int k = 0; k < 8; k++) e[k] = __ldg(&g_cedge[j + k]);
        float2 v[8];
        #pragma unroll
        for (int k = 0; k < 8; k++)
            v[k] = __half22float2(__ldg(&g_xh0[(e[k] >> 15) * 32 + lane]));
        #pragma unroll
        for (int k = 0; k < 8; k++) {
            float n = (float)(e[k] & 0x7FFFu) * wdq;
            acc.x += n * v[k].x;
            acc.y += n * v[k].y;
        }
    }
    for (; j < end; j++) {
        unsigned e0 = __ldg(&g_cedge[j]);
        float2 v0 = __half22float2(__ldg(&g_xh0[(e0 >> 15) * 32 + lane]));
        float n = (float)(e0 & 0x7FFFu) * wdq;
        acc.x += n * v0.x;
        acc.y += n * v0.y;
    }

    float2 bb = ((const float2*)b)[lane];
    g_hh[warp * 32 + lane] = __floats2half2_rn(fmaxf(acc.x * di + bb.x, 0.0f),
                                               fmaxf(acc.y * di + bb.y, 0.0f));
}

// ---------------- 6. gemm-L1: g_xh1 = g_hh @ W1 (fp16 in, fp16 out) --------------
__global__ void __launch_bounds__(256)
k_gemm1(const float* __restrict__ W)
{
    __shared__ float4 hs4[64][17];
    __shared__ float4 ws4[64][17];
    int tid = threadIdx.x;
    int r0  = blockIdx.x * 64;

    #pragma unroll
    for (int ii = 0; ii < 4; ii++) {
        int i = ii * 256 + tid;
        int r = i >> 4, c = i & 15;
        int row = r0 + r;
        float4 v = make_float4(0.f, 0.f, 0.f, 0.f);
        if (row < NN) {
            float2 f0 = __half22float2(g_hh[row * 32 + c * 2]);
            float2 f1 = __half22float2(g_hh[row * 32 + c * 2 + 1]);
            v = make_float4(f0.x, f0.y, f1.x, f1.y);
        }
        hs4[r][c] = v;
        ws4[r][c] = ((const float4*)W)[i];
    }
    __syncthreads();

    int tx = tid & 15, ty = tid >> 4;
    float4 acc[4];
    #pragma unroll
    for (int r = 0; r < 4; r++) acc[r] = make_float4(0.f, 0.f, 0.f, 0.f);
    #pragma unroll
    for (int kg = 0; kg < 16; kg++) {
        float4 w0 = ws4[kg * 4 + 0][tx];
        float4 w1 = ws4[kg * 4 + 1][tx];
        float4 w2 = ws4[kg * 4 + 2][tx];
        float4 w3 = ws4[kg * 4 + 3][tx];
        #pragma unroll
        for (int r = 0; r < 4; r++) {
            float4 a = hs4[ty * 4 + r][kg];
            acc[r].x += a.x * w0.x + a.y * w1.x + a.z * w2.x + a.w * w3.x;
            acc[r].y += a.x * w0.y + a.y * w1.y + a.z * w2.y + a.w * w3.y;
            acc[r].z += a.x * w0.z + a.y * w1.z + a.z * w2.z + a.w * w3.z;
            acc[r].w += a.x * w0.w + a.y * w1.w + a.z * w2.w + a.w * w3.w;
        }
    }
    #pragma unroll
    for (int r = 0; r < 4; r++) {
        int row = r0 + ty * 4 + r;
        if (row < NN) {
            g_xh1[row * 32 + tx * 2]     = __floats2half2_rn(acc[r].x, acc[r].y);
            g_xh1[row * 32 + tx * 2 + 1] = __floats2half2_rn(acc[r].z, acc[r].w);
        }
    }
}

// ---------------- per-node layer-1 aggregation (warp-collective) -----------------
__device__ __forceinline__ float2 agg1_node(int node, int lane, float2 bb)
{
    int start = g_rs[node];
    int end   = g_rs[node + 1];
    float di  = g_dinv[node];

    float2 xs  = __half22float2(__ldg(&g_xh1[node * 32 + lane]));
    float2 acc = make_float2(xs.x * di, xs.y * di);

    const float wdq = 1.0f / WQ_SCALE;
    int cnt = end - start;
    int n8  = start + (cnt & ~7);
    int j = start;
    for (; j < n8; j += 8) {
        unsigned e[8];
        #pragma unroll
        for (int k = 0; k < 8; k++) e[k] = __ldg(&g_cedge[j + k]);
        float2 v[8];
        #pragma unroll
        for (int k = 0; k < 8; k++)
            v[k] = __half22float2(__ldg(&g_xh1[(e[k] >> 15) * 32 + lane]));
        #pragma unroll
        for (int k = 0; k < 8; k++) {
            float n = (float)(e[k] & 0x7FFFu) * wdq;
            acc.x += n * v[k].x;
            acc.y += n * v[k].y;
        }
    }
    for (; j < end; j++) {
        unsigned e0 = __ldg(&g_cedge[j]);
        float2 v0 = __half22float2(__ldg(&g_xh1[(e0 >> 15) * 32 + lane]));
        float n = (float)(e0 & 0x7FFFu) * wdq;
        acc.x += n * v0.x;
        acc.y += n * v0.y;
    }
    return make_float2(fmaxf(acc.x * di + bb.x, 0.0f),
                       fmaxf(acc.y * di + bb.y, 0.0f));
}

// ---------------- 7. fused agg1 + MLP head (one warp per batch row) --------------
// lane owns columns (2*lane, 2*lane+1) of se/re; tx[lane] for the 32 tx cols.
__global__ void k_mlp(const int* __restrict__ tsl, const int* __restrict__ trl,
                      const int* __restrict__ ptr, const float* __restrict__ txf,
                      const float* __restrict__ b1v,
                      const float* __restrict__ Wtx, const float* __restrict__ btx,
                      const float* __restrict__ Wc1, const float* __restrict__ bc1,
                      const float* __restrict__ g1,  const float* __restrict__ beta1,
                      const float* __restrict__ Wc2, const float* __restrict__ bc2,
                      const float* __restrict__ g2,  const float* __restrict__ beta2,
                      const float* __restrict__ Wc3, const float* __restrict__ bc3,
                      float* __restrict__ out)
{
    __shared__ float Wc1s[160 * 64];
    for (int i = threadIdx.x; i < 160 * 64; i += blockDim.x) Wc1s[i] = Wc1[i];
    __syncthreads();

    const int lane = threadIdx.x & 31;
    const int row  = blockIdx.x * (blockDim.x >> 5) + (threadIdx.x >> 5);
    if (row >= BB) return;

    const float invs = rsqrtf(1.0f + BN_EPS);
    const unsigned FULL = 0xffffffffu;

    int off  = ptr[row];
    int sidx = tsl[row] + off;
    int ridx = trl[row] + off;

    // layer-1 aggregation for this row's two nodes (warp-collective)
    float2 bb = ((const float2*)b1v)[lane];
    float2 se = agg1_node(sidx, lane, bb);
    float2 re = agg1_node(ridx, lane, bb);

    // tx = relu(txf @ Wtx + btx); lane holds tx[lane]
    float f = (lane < DTXF) ? txf[row * DTXF + lane] : 0.0f;
    float acct = __ldg(&btx[lane]);
    #pragma unroll
    for (int k = 0; k < DTXF; k++) {
        float tk = __shfl_sync(FULL, f, k);
        acct += tk * __ldg(&Wtx[k * DTX + lane]);
    }
    float txv = fmaxf(acct, 0.0f);

    // z1 = relu(bn(z @ Wc1 + bc1)); z = [se(64), re(64), tx(32)]
    float2 a = make_float2(0.f, 0.f);
    #pragma unroll
    for (int k = 0; k < 64; k++) {               // sender block
        float zk = __shfl_sync(FULL, (k & 1) ? se.y : se.x, k >> 1);
        float2 w = *(const float2*)&Wc1s[k * 64 + 2 * lane];
        a.x += zk * w.x;
        a.y += zk * w.y;
    }
    #pragma unroll
    for (int k = 0; k < 64; k++) {               // receiver block
        float zk = __shfl_sync(FULL, (k & 1) ? re.y : re.x, k >> 1);
        float2 w = *(const float2*)&Wc1s[(64 + k) * 64 + 2 * lane];
        a.x += zk * w.x;
        a.y += zk * w.y;
    }
    #pragma unroll
    for (int k = 0; k < 32; k++) {               // tx block
        float zk = __shfl_sync(FULL, txv, k);
        float2 w = *(const float2*)&Wc1s[(128 + k) * 64 + 2 * lane];
        a.x += zk * w.x;
        a.y += zk * w.y;
    }
    int c0 = 2 * lane, c1 = 2 * lane + 1;
    float z1x = fmaxf((a.x + __ldg(&bc1[c0])) * (__ldg(&g1[c0]) * invs) + __ldg(&beta1[c0]), 0.0f);
    float z1y = fmaxf((a.y + __ldg(&bc1[c1])) * (__ldg(&g1[c1]) * invs) + __ldg(&beta1[c1]), 0.0f);

    // z2 = relu(bn(z1 @ Wc2 + bc2)); lane owns col lane
    float acc2 = 0.0f;
    #pragma unroll
    for (int k = 0; k < DH; k++) {
        float zk = __shfl_sync(FULL, (k & 1) ? z1y : z1x, k >> 1);
        acc2 += zk * __ldg(&Wc2[k * 32 + lane]);
    }
    float z2v = fmaxf((acc2 + __ldg(&bc2[lane])) * (__ldg(&g2[lane]) * invs) + __ldg(&beta2[lane]), 0.0f);

    float p = z2v * __ldg(&Wc3[lane]);
    #pragma unroll
    for (int o = 16; o > 0; o >>= 1) p += __shfl_xor_sync(FULL, p, o);
    if (lane == 0) out[row] = p + __ldg(&bc3[0]);
}

// =============================== launch ========================================
extern "C" void kernel_launch(void* const* d_in, const int* in_sizes, int n_in,
                              void* d_out, int out_size)
{
    const int*   ids  = (const int*)  d_in[0];
    const int*   ei   = (const int*)  d_in[1];
    const float* ew   = (const float*)d_in[2];
    const int*   tsl  = (const int*)  d_in[3];
    const int*   trl  = (const int*)  d_in[4];
    const int*   ptr  = (const int*)  d_in[5];
    const float* txf  = (const float*)d_in[6];
    const float* emb  = (const float*)d_in[7];
    const float* W0   = (const float*)d_in[8];
    const float* b0   = (const float*)d_in[9];
    const float* W1   = (const float*)d_in[10];
    const float* b1   = (const float*)d_in[11];
    const float* Wtx  = (const float*)d_in[12];
    const float* btx  = (const float*)d_in[13];
    const float* Wc1  = (const float*)d_in[14];
    const float* bc1  = (const float*)d_in[15];
    const float* g1   = (const float*)d_in[16];
    const float* beta1= (const float*)d_in[17];
    const float* Wc2  = (const float*)d_in[18];
    const float* bc2  = (const float*)d_in[19];
    const float* g2   = (const float*)d_in[20];
    const float* beta2= (const float*)d_in[21];
    const float* Wc3  = (const float*)d_in[22];
    const float* bc3  = (const float*)d_in[23];
    float* out = (float*)d_out;

    const int* src = ei;
    const int* dst = ei + NE;

    // 1 count (rank+wq packed)
    k_cnt<<<CNT4B, 256>>>(dst, ew);
    // 2-3 scan + dinv
    k_scan1 <<<NSCAN, SCAN_BLK>>>();
    k_scan23<<<(NN + 255) / 256, 256>>>();
    // 4 CSR fill ∥ gemm-L0 -> g_xh0
    k_fillgemm0<<<FILL4B + GEMMB, 256>>>(W0, ids, emb, src, dst);
    // 5 dense agg0 -> g_hh (fp16)
    k_agg0<<<(NN + 7) / 8, 256>>>(b0);
    // 6 gemm-L1 -> g_xh1
    k_gemm1<<<GEMMB, 256>>>(W1);
    // 7 fused agg1 + MLP head
    k_mlp<<<BB / 8, 256>>>(tsl, trl, ptr, txf, b1,
                           Wtx, btx, Wc1, bc1, g1, beta1,
                           Wc2, bc2, g2, beta2, Wc3, bc3, out);
}